// round 16
// baseline (speedup 1.0000x reference)
#include <cuda_runtime.h>
#include <math.h>

// Problem shape (fixed by reference)
#define N_ROWS 262144
#define D_DIM  512
#define V_DIM  512

#define GRID   608                      // 152 SMs x 4 resident CTAs -> single wave
#define BLOCK  256
#define WARPS  (BLOCK / 32)
#define TOTAL_WARPS (GRID * WARPS)      // 4864
#define N_GROUPS (N_ROWS / 2)           // 131072 groups of 2 rows

#define BTIES     4     // tie indices kept per block
#define MAX_TIES 16     // tie indices kept globally

// ---- device scratch (static zero-init; g_done reset by last block) ----
__device__ float g_blockmax[GRID];
__device__ float g_blocksum[GRID];
__device__ int   g_btiecnt[GRID];
__device__ int   g_btieidx[GRID * BTIES];
__device__ unsigned int g_done;   // zero-initialized; reset to 0 each launch

__device__ __forceinline__ float dot16(float4 a0, float4 a1, float4 a2, float4 a3,
                                       float4 q0, float4 q1, float4 q2, float4 q3)
{
    float s = 0.f;
    s = fmaf(a0.x, q0.x, s); s = fmaf(a0.y, q0.y, s);
    s = fmaf(a0.z, q0.z, s); s = fmaf(a0.w, q0.w, s);
    s = fmaf(a1.x, q1.x, s); s = fmaf(a1.y, q1.y, s);
    s = fmaf(a1.z, q1.z, s); s = fmaf(a1.w, q1.w, s);
    s = fmaf(a2.x, q2.x, s); s = fmaf(a2.y, q2.y, s);
    s = fmaf(a2.z, q2.z, s); s = fmaf(a2.w, q2.w, s);
    s = fmaf(a3.x, q3.x, s); s = fmaf(a3.y, q3.y, s);
    s = fmaf(a3.z, q3.z, s); s = fmaf(a3.w, q3.w, s);
    return s;
}

__global__ __launch_bounds__(BLOCK, 4) void fused_kernel(
    const float* __restrict__ query,
    const float* __restrict__ keys,
    const float* __restrict__ values,
    float* __restrict__ out)
{
    const int tid   = threadIdx.x;
    const int lane  = tid & 31;
    const int wid   = tid >> 5;
    const int gwarp = blockIdx.x * WARPS + wid;

    // Query register-resident: lane l owns q 16B-chunks l, l+32, l+64, l+96
    const float4* q4 = reinterpret_cast<const float4*>(query);
    const float4 q0 = q4[lane];
    const float4 q1 = q4[lane + 32];
    const float4 q2 = q4[lane + 64];
    const float4 q3 = q4[lane + 96];

    // per-lane online softmax state (only lanes 0..1 accumulate)
    float m = -INFINITY, s = 0.f;
    int   idx = -1, idx2 = -1;

    #pragma unroll 1
    for (int g = gwarp; g < N_GROUPS; g += TOTAL_WARPS) {
        const int row = g * 2;
        const float4* kr0 = reinterpret_cast<const float4*>(keys + (size_t)(row + 0) * D_DIM);
        const float4* kr1 = reinterpret_cast<const float4*>(keys + (size_t)(row + 1) * D_DIM);

        // 8 streaming LDG.128 in flight
        float4 a0 = __ldcs(kr0 + lane);
        float4 a1 = __ldcs(kr0 + lane + 32);
        float4 a2 = __ldcs(kr0 + lane + 64);
        float4 a3 = __ldcs(kr0 + lane + 96);
        float4 b0 = __ldcs(kr1 + lane);
        float4 b1 = __ldcs(kr1 + lane + 32);
        float4 b2 = __ldcs(kr1 + lane + 64);
        float4 b3 = __ldcs(kr1 + lane + 96);

        float s0 = dot16(a0, a1, a2, a3, q0, q1, q2, q3);
        float s1 = dot16(b0, b1, b2, b3, q0, q1, q2, q3);

        // ---- transposed reduction: 5 shuffles for 2 rows ----
        float u = (lane & 1) ? s1 : s0;
        float v = (lane & 1) ? s0 : s1;
        u += __shfl_xor_sync(0xFFFFFFFFu, v, 1);
        u += __shfl_xor_sync(0xFFFFFFFFu, u, 2);
        u += __shfl_xor_sync(0xFFFFFFFFu, u, 4);
        u += __shfl_xor_sync(0xFFFFFFFFu, u, 8);
        u += __shfl_xor_sync(0xFFFFFFFFu, u, 16);
        // lane l holds the full logit of row (row + (l&1)), replicated x16

        if (lane < 2) {
            float x = u;
            if (x > m) {
                s = s * __expf(m - x) + 1.0f;   // expf(-inf)=0 on first hit
                m = x; idx = row + lane; idx2 = -1;
            } else if (x == m) {
                s += 1.0f; idx2 = row + lane;
            } else {
                s += __expf(x - m);
            }
        }
    }

    // ---- warp-level guarded online merge of (m, s) ----
    float wm = m, ws = s;
    #pragma unroll
    for (int k = 16; k > 0; k >>= 1) {
        float om = __shfl_xor_sync(0xFFFFFFFFu, wm, k);
        float os = __shfl_xor_sync(0xFFFFFFFFu, ws, k);
        float nm = fmaxf(wm, om);
        float fa = (wm == nm) ? 1.0f : __expf(wm - nm);
        float fb = (om == nm) ? 1.0f : __expf(om - nm);
        ws = ws * fa + os * fb;
        wm = nm;
    }

    // ---- block combine ----
    __shared__ float s_wmax[WARPS];
    __shared__ float s_wsum[WARPS];
    __shared__ int   s_tiecnt;
    __shared__ int   s_tieidx[BTIES];
    __shared__ float s_bmax;
    __shared__ int   s_islast;

    if (lane == 0) { s_wmax[wid] = wm; s_wsum[wid] = ws; }
    if (tid == 0) s_tiecnt = 0;
    __syncthreads();

    if (tid == 0) {
        float bmax = -INFINITY;
        #pragma unroll
        for (int w = 0; w < WARPS; ++w) bmax = fmaxf(bmax, s_wmax[w]);
        float bsum = 0.f;
        #pragma unroll
        for (int w = 0; w < WARPS; ++w) bsum += s_wsum[w] * __expf(s_wmax[w] - bmax);
        s_bmax = bmax;
        g_blockmax[blockIdx.x] = bmax;
        g_blocksum[blockIdx.x] = bsum;
    }
    __syncthreads();

    // tie recording against block max (bit-exact: same stored values)
    if (m == s_bmax) {
        int p = atomicAdd(&s_tiecnt, 1);
        if (p < BTIES) s_tieidx[p] = idx;
        if (idx2 >= 0) {
            int p2 = atomicAdd(&s_tiecnt, 1);
            if (p2 < BTIES) s_tieidx[p2] = idx2;
        }
    }
    __syncthreads();

    if (tid == 0) {
        int c = s_tiecnt; if (c > BTIES) c = BTIES;
        g_btiecnt[blockIdx.x] = c;
        for (int j = 0; j < c; ++j) g_btieidx[blockIdx.x * BTIES + j] = s_tieidx[j];
        __threadfence();
        unsigned int ticket = atomicAdd(&g_done, 1u);
        s_islast = (ticket == GRID - 1);
    }
    __syncthreads();
    if (!s_islast) return;

    // ================= last block: final reduction + output =================
    __shared__ float s_red[WARPS];
    __shared__ float s_M, s_Z;
    __shared__ int   f_cnt;
    __shared__ int   f_idx[MAX_TIES];

    float gm = -INFINITY;
    for (int b = tid; b < GRID; b += BLOCK) gm = fmaxf(gm, g_blockmax[b]);
    #pragma unroll
    for (int k = 16; k > 0; k >>= 1) gm = fmaxf(gm, __shfl_xor_sync(0xFFFFFFFFu, gm, k));
    if (lane == 0) s_red[wid] = gm;
    if (tid == 0) f_cnt = 0;
    __syncthreads();
    if (tid == 0) {
        float M = -INFINITY;
        #pragma unroll
        for (int w = 0; w < WARPS; ++w) M = fmaxf(M, s_red[w]);
        s_M = M;
    }
    __syncthreads();
    const float M = s_M;

    float z = 0.f;
    for (int b = tid; b < GRID; b += BLOCK) {
        float bm = g_blockmax[b];
        z += g_blocksum[b] * __expf(bm - M);
        if (bm == M) {
            int c = g_btiecnt[b];
            for (int j = 0; j < c; ++j) {
                int p = atomicAdd(&f_cnt, 1);
                if (p < MAX_TIES) f_idx[p] = g_btieidx[b * BTIES + j];
            }
        }
    }
    #pragma unroll
    for (int k = 16; k > 0; k >>= 1) z += __shfl_xor_sync(0xFFFFFFFFu, z, k);
    if (lane == 0) s_red[wid] = z;
    __syncthreads();
    if (tid == 0) {
        float Z = 0.f;
        #pragma unroll
        for (int w = 0; w < WARPS; ++w) Z += s_red[w];
        s_Z = Z;
        g_done = 0;   // reset for next graph replay
    }
    __syncthreads();

    const float invZ = 1.0f / s_Z;
    int cnt = f_cnt; if (cnt > MAX_TIES) cnt = MAX_TIES;
    for (int v = tid; v < V_DIM; v += BLOCK) {
        float acc = 0.f;
        for (int j = 0; j < cnt; ++j)
            acc += values[(size_t)f_idx[j] * V_DIM + v];
        out[v] = acc * invZ;
    }
}

// ---------------------------------------------------------------------------
extern "C" void kernel_launch(void* const* d_in, const int* in_sizes, int n_in,
                              void* d_out, int out_size)
{
    const float* query  = (const float*)d_in[0];  // [512]
    const float* keys   = (const float*)d_in[1];  // [262144, 512]
    const float* values = (const float*)d_in[2];  // [262144, 512]
    float* out = (float*)d_out;                   // [512]

    fused_kernel<<<GRID, BLOCK>>>(query, keys, values, out);
}

// round 17
// speedup vs baseline: 1.0165x; 1.0165x over previous
#include <cuda_runtime.h>
#include <math.h>

// Problem shape (fixed by reference)
#define N_ROWS 262144
#define D_DIM  512
#define V_DIM  512

#define GRID   608                      // 152 SMs x 4 resident CTAs -> single wave
#define BLOCK  256
#define WARPS  (BLOCK / 32)
#define TOTAL_WARPS (GRID * WARPS)      // 4864
#define N_GROUPS (N_ROWS / 2)           // 131072 groups of 2 rows

#define BTIES     4     // tie indices kept per block
#define MAX_TIES 16     // tie indices kept globally

// ---- device scratch (static zero-init; g_done reset by last block) ----
__device__ float g_blockmax[GRID];
__device__ float g_blocksum[GRID];
__device__ int   g_btiecnt[GRID];
__device__ int   g_btieidx[GRID * BTIES];
__device__ unsigned int g_done;   // zero-initialized; reset to 0 each launch

__device__ __forceinline__ float dot16(float4 a0, float4 a1, float4 a2, float4 a3,
                                       float4 q0, float4 q1, float4 q2, float4 q3)
{
    float s = 0.f;
    s = fmaf(a0.x, q0.x, s); s = fmaf(a0.y, q0.y, s);
    s = fmaf(a0.z, q0.z, s); s = fmaf(a0.w, q0.w, s);
    s = fmaf(a1.x, q1.x, s); s = fmaf(a1.y, q1.y, s);
    s = fmaf(a1.z, q1.z, s); s = fmaf(a1.w, q1.w, s);
    s = fmaf(a2.x, q2.x, s); s = fmaf(a2.y, q2.y, s);
    s = fmaf(a2.z, q2.z, s); s = fmaf(a2.w, q2.w, s);
    s = fmaf(a3.x, q3.x, s); s = fmaf(a3.y, q3.y, s);
    s = fmaf(a3.z, q3.z, s); s = fmaf(a3.w, q3.w, s);
    return s;
}

__global__ __launch_bounds__(BLOCK, 4) void fused_kernel(
    const float* __restrict__ query,
    const float* __restrict__ keys,
    const float* __restrict__ values,
    float* __restrict__ out)
{
    const int tid   = threadIdx.x;
    const int lane  = tid & 31;
    const int wid   = tid >> 5;
    const int gwarp = blockIdx.x * WARPS + wid;

    // Query register-resident: lane l owns q 16B-chunks l, l+32, l+64, l+96
    const float4* q4 = reinterpret_cast<const float4*>(query);
    const float4 q0 = q4[lane];
    const float4 q1 = q4[lane + 32];
    const float4 q2 = q4[lane + 64];
    const float4 q3 = q4[lane + 96];

    // per-lane online softmax state (only lanes 0..1 accumulate)
    float m = -INFINITY, s = 0.f;
    int   idx = -1, idx2 = -1;

    #pragma unroll 1
    for (int g = gwarp; g < N_GROUPS; g += TOTAL_WARPS) {
        const int row = g * 2;
        const float4* kr0 = reinterpret_cast<const float4*>(keys + (size_t)(row + 0) * D_DIM);
        const float4* kr1 = reinterpret_cast<const float4*>(keys + (size_t)(row + 1) * D_DIM);

        // 8 streaming LDG.128 in flight
        float4 a0 = __ldcs(kr0 + lane);
        float4 a1 = __ldcs(kr0 + lane + 32);
        float4 a2 = __ldcs(kr0 + lane + 64);
        float4 a3 = __ldcs(kr0 + lane + 96);
        float4 b0 = __ldcs(kr1 + lane);
        float4 b1 = __ldcs(kr1 + lane + 32);
        float4 b2 = __ldcs(kr1 + lane + 64);
        float4 b3 = __ldcs(kr1 + lane + 96);

        float s0 = dot16(a0, a1, a2, a3, q0, q1, q2, q3);
        float s1 = dot16(b0, b1, b2, b3, q0, q1, q2, q3);

        // ---- transposed reduction: 5 shuffles for 2 rows ----
        float u = (lane & 1) ? s1 : s0;
        float v = (lane & 1) ? s0 : s1;
        u += __shfl_xor_sync(0xFFFFFFFFu, v, 1);
        u += __shfl_xor_sync(0xFFFFFFFFu, u, 2);
        u += __shfl_xor_sync(0xFFFFFFFFu, u, 4);
        u += __shfl_xor_sync(0xFFFFFFFFu, u, 8);
        u += __shfl_xor_sync(0xFFFFFFFFu, u, 16);
        // lane l holds the full logit of row (row + (l&1)), replicated x16

        if (lane < 2) {
            float x = u;
            if (x > m) {
                s = s * __expf(m - x) + 1.0f;   // expf(-inf)=0 on first hit
                m = x; idx = row + lane; idx2 = -1;
            } else if (x == m) {
                s += 1.0f; idx2 = row + lane;
            } else {
                s += __expf(x - m);
            }
        }
    }

    // ---- warp-level guarded online merge of (m, s) ----
    float wm = m, ws = s;
    #pragma unroll
    for (int k = 16; k > 0; k >>= 1) {
        float om = __shfl_xor_sync(0xFFFFFFFFu, wm, k);
        float os = __shfl_xor_sync(0xFFFFFFFFu, ws, k);
        float nm = fmaxf(wm, om);
        float fa = (wm == nm) ? 1.0f : __expf(wm - nm);
        float fb = (om == nm) ? 1.0f : __expf(om - nm);
        ws = ws * fa + os * fb;
        wm = nm;
    }

    // ---- block combine ----
    __shared__ float s_wmax[WARPS];
    __shared__ float s_wsum[WARPS];
    __shared__ int   s_tiecnt;
    __shared__ int   s_tieidx[BTIES];
    __shared__ float s_bmax;
    __shared__ int   s_islast;

    if (lane == 0) { s_wmax[wid] = wm; s_wsum[wid] = ws; }
    if (tid == 0) s_tiecnt = 0;
    __syncthreads();

    if (tid == 0) {
        float bmax = -INFINITY;
        #pragma unroll
        for (int w = 0; w < WARPS; ++w) bmax = fmaxf(bmax, s_wmax[w]);
        float bsum = 0.f;
        #pragma unroll
        for (int w = 0; w < WARPS; ++w) bsum += s_wsum[w] * __expf(s_wmax[w] - bmax);
        s_bmax = bmax;
        g_blockmax[blockIdx.x] = bmax;
        g_blocksum[blockIdx.x] = bsum;
    }
    __syncthreads();

    // tie recording against block max (bit-exact: same stored values)
    if (m == s_bmax) {
        int p = atomicAdd(&s_tiecnt, 1);
        if (p < BTIES) s_tieidx[p] = idx;
        if (idx2 >= 0) {
            int p2 = atomicAdd(&s_tiecnt, 1);
            if (p2 < BTIES) s_tieidx[p2] = idx2;
        }
    }
    __syncthreads();

    if (tid == 0) {
        int c = s_tiecnt; if (c > BTIES) c = BTIES;
        g_btiecnt[blockIdx.x] = c;
        for (int j = 0; j < c; ++j) g_btieidx[blockIdx.x * BTIES + j] = s_tieidx[j];
        __threadfence();
        unsigned int ticket = atomicAdd(&g_done, 1u);
        s_islast = (ticket == GRID - 1);
    }
    __syncthreads();
    if (!s_islast) return;

    // ================= last block: final reduction + output =================
    __shared__ float s_red[WARPS];
    __shared__ float s_M, s_Z;
    __shared__ int   f_cnt;
    __shared__ int   f_idx[MAX_TIES];

    float gm = -INFINITY;
    for (int b = tid; b < GRID; b += BLOCK) gm = fmaxf(gm, g_blockmax[b]);
    #pragma unroll
    for (int k = 16; k > 0; k >>= 1) gm = fmaxf(gm, __shfl_xor_sync(0xFFFFFFFFu, gm, k));
    if (lane == 0) s_red[wid] = gm;
    if (tid == 0) f_cnt = 0;
    __syncthreads();
    if (tid == 0) {
        float M = -INFINITY;
        #pragma unroll
        for (int w = 0; w < WARPS; ++w) M = fmaxf(M, s_red[w]);
        s_M = M;
    }
    __syncthreads();
    const float M = s_M;

    float z = 0.f;
    for (int b = tid; b < GRID; b += BLOCK) {
        float bm = g_blockmax[b];
        z += g_blocksum[b] * __expf(bm - M);
        if (bm == M) {
            int c = g_btiecnt[b];
            for (int j = 0; j < c; ++j) {
                int p = atomicAdd(&f_cnt, 1);
                if (p < MAX_TIES) f_idx[p] = g_btieidx[b * BTIES + j];
            }
        }
    }
    #pragma unroll
    for (int k = 16; k > 0; k >>= 1) z += __shfl_xor_sync(0xFFFFFFFFu, z, k);
    if (lane == 0) s_red[wid] = z;
    __syncthreads();
    if (tid == 0) {
        float Z = 0.f;
        #pragma unroll
        for (int w = 0; w < WARPS; ++w) Z += s_red[w];
        s_Z = Z;
        g_done = 0;   // reset for next graph replay
    }
    __syncthreads();

    const float invZ = 1.0f / s_Z;
    int cnt = f_cnt; if (cnt > MAX_TIES) cnt = MAX_TIES;
    for (int v = tid; v < V_DIM; v += BLOCK) {
        float acc = 0.f;
        for (int j = 0; j < cnt; ++j)
            acc += values[(size_t)f_idx[j] * V_DIM + v];
        out[v] = acc * invZ;
    }
}

// ---------------------------------------------------------------------------
extern "C" void kernel_launch(void* const* d_in, const int* in_sizes, int n_in,
                              void* d_out, int out_size)
{
    const float* query  = (const float*)d_in[0];  // [512]
    const float* keys   = (const float*)d_in[1];  // [262144, 512]
    const float* values = (const float*)d_in[2];  // [262144, 512]
    float* out = (float*)d_out;                   // [512]

    fused_kernel<<<GRID, BLOCK>>>(query, keys, values, out);
}